// round 8
// baseline (speedup 1.0000x reference)
#include <cuda_runtime.h>

#define N_NODES 10000
#define N_EDGES 320000
#define HID 128
#define H3 384
#define NRBF 20
#define EPB 32      // edges per block (edge kernel)
#define KCH 16      // Wf2 k-rows per staged chunk
#define NCHUNK (HID / KCH)   // 8

typedef unsigned long long ull;

// scratch
__device__ float g_x[N_NODES * H3];   // node MLP output [N, 384]
__device__ int g_idx64;
__device__ int g_hist[N_NODES];
__device__ int g_cursor[N_NODES];
__device__ int g_perm[N_EDGES];       // edge ids sorted by target

__device__ __forceinline__ float silu_f(float v) {
    return v / (1.0f + __expf(-v));
}
__device__ __forceinline__ ull pack2(float lo, float hi) {
    ull r;
    asm("mov.b64 %0,{%1,%2};" : "=l"(r) : "f"(lo), "f"(hi));
    return r;
}
__device__ __forceinline__ void unpack2(ull v, float& lo, float& hi) {
    asm("mov.b64 {%0,%1},%2;" : "=f"(lo), "=f"(hi) : "l"(v));
}
// packed f32x2 FMA — 2x fma-pipe throughput
__device__ __forceinline__ ull fma2(ull a, ull b, ull c) {
    ull d;
    asm("fma.rn.f32x2 %0,%1,%2,%3;" : "=l"(d) : "l"(a), "l"(b), "l"(c));
    return d;
}
__device__ __forceinline__ void red_add_v2(float* p, float a, float b) {
    asm volatile("red.global.add.v2.f32 [%0],{%1,%2};"
                 :: "l"(p), "f"(a), "f"(b) : "memory");
}
__device__ __forceinline__ void cp_async16(void* sdst, const void* gsrc) {
    unsigned s = (unsigned)__cvta_generic_to_shared(sdst);
    asm volatile("cp.async.cg.shared.global [%0],[%1],16;" :: "r"(s), "l"(gsrc));
}
__device__ __forceinline__ void cp_commit() {
    asm volatile("cp.async.commit_group;");
}
template <int N>
__device__ __forceinline__ void cp_wait() {
    asm volatile("cp.async.wait_group %0;" :: "n"(N));
}

// ---------------------------------------------------------------------------
// Kernel 1: out = concat(q, mu); detect idx dtype; zero histogram.
// ---------------------------------------------------------------------------
__global__ void init_out(const float* __restrict__ q,
                         const float* __restrict__ mu,
                         float* __restrict__ out,
                         const int* __restrict__ ei32) {
    if (blockIdx.x == 0 && threadIdx.x == 0) {
        int flag = 1;
        #pragma unroll
        for (int i = 0; i < 16; i++)
            if (ei32[2 * i + 1] != 0) flag = 0;
        g_idx64 = flag;
    }
    int i = blockIdx.x * blockDim.x + threadIdx.x;
    if (i < N_NODES) g_hist[i] = 0;
    const int nq4 = N_NODES * HID / 4;
    const int nm4 = N_NODES * H3 / 4;
    float4* o4 = (float4*)out;
    if (i < nq4)            o4[i] = ((const float4*)q)[i];
    else if (i < nq4 + nm4) o4[i] = ((const float4*)mu)[i - nq4];
}

// --------------------------- counting sort by target -----------------------
__global__ void hist_kernel(const int* __restrict__ ei32,
                            const long long* __restrict__ ei64) {
    int e = blockIdx.x * blockDim.x + threadIdx.x;
    if (e < N_EDGES) {
        int t = g_idx64 ? (int)ei64[e] : ei32[e];
        atomicAdd(&g_hist[t], 1);
    }
}

__global__ __launch_bounds__(1024) void scan_kernel() {
    // exclusive prefix sum over 10000 bins; 1 block, 10 bins/thread
    __shared__ int part[1024];
    const int tid = threadIdx.x;
    const int base = tid * 10;
    int local[10];
    int s = 0;
    #pragma unroll
    for (int j = 0; j < 10; j++) {
        int v = (base + j < N_NODES) ? g_hist[base + j] : 0;
        local[j] = s;
        s += v;
    }
    part[tid] = s;
    __syncthreads();
    const int own = s;
    for (int d = 1; d < 1024; d <<= 1) {
        int v = (tid >= d) ? part[tid - d] : 0;
        __syncthreads();
        part[tid] += v;
        __syncthreads();
    }
    int excl = part[tid] - own;
    #pragma unroll
    for (int j = 0; j < 10; j++)
        if (base + j < N_NODES) g_cursor[base + j] = excl + local[j];
}

__global__ void scatter_kernel(const int* __restrict__ ei32,
                               const long long* __restrict__ ei64) {
    int e = blockIdx.x * blockDim.x + threadIdx.x;
    if (e < N_EDGES) {
        int t = g_idx64 ? (int)ei64[e] : ei32[e];
        int pos = atomicAdd(&g_cursor[t], 1);
        g_perm[pos] = e;
    }
}

// ---------------------------------------------------------------------------
// Kernel 2: node MLP with f32x2 packed math. 16 nodes/block.
// ---------------------------------------------------------------------------
__global__ __launch_bounds__(384) void node_mlp(const float* __restrict__ q,
                                                const float* __restrict__ W1,
                                                const float* __restrict__ b1,
                                                const float* __restrict__ W2,
                                                const float* __restrict__ b2) {
    __shared__ float qs[16 * HID];
    __shared__ ull qs2[HID * 8];
    __shared__ ull t1p[H3 * 8];
    const int n0 = blockIdx.x * 16;
    const int tid = threadIdx.x;

    for (int i = tid; i < 16 * HID; i += 384) qs[i] = q[n0 * HID + i];
    __syncthreads();
    for (int i = tid; i < HID * 8; i += 384) {
        int k = i >> 3, j = i & 7;
        qs2[k * 8 + j] = pack2(qs[(2 * j) * HID + k], qs[(2 * j + 1) * HID + k]);
    }
    __syncthreads();

    const int c = tid;
    {
        ull a[8];
        float bb = __ldg(&b1[c]);
        ull bp = pack2(bb, bb);
        #pragma unroll
        for (int j = 0; j < 8; j++) a[j] = bp;
        #pragma unroll 4
        for (int k = 0; k < HID; k++) {
            float w = __ldg(&W1[k * H3 + c]);
            ull ww = pack2(w, w);
            const ulonglong2* qp = (const ulonglong2*)(qs2 + k * 8);
            ulonglong2 p0 = qp[0], p1 = qp[1], p2 = qp[2], p3 = qp[3];
            a[0] = fma2(p0.x, ww, a[0]); a[1] = fma2(p0.y, ww, a[1]);
            a[2] = fma2(p1.x, ww, a[2]); a[3] = fma2(p1.y, ww, a[3]);
            a[4] = fma2(p2.x, ww, a[4]); a[5] = fma2(p2.y, ww, a[5]);
            a[6] = fma2(p3.x, ww, a[6]); a[7] = fma2(p3.y, ww, a[7]);
        }
        #pragma unroll
        for (int j = 0; j < 8; j++) {
            float lo, hi;
            unpack2(a[j], lo, hi);
            t1p[c * 8 + j] = pack2(silu_f(lo), silu_f(hi));
        }
    }
    __syncthreads();
    {
        ull a[8];
        float bb = __ldg(&b2[c]);
        ull bp = pack2(bb, bb);
        #pragma unroll
        for (int j = 0; j < 8; j++) a[j] = bp;
        #pragma unroll 4
        for (int k = 0; k < H3; k++) {
            float w = __ldg(&W2[k * H3 + c]);
            ull ww = pack2(w, w);
            const ulonglong2* tp = (const ulonglong2*)(t1p + k * 8);
            ulonglong2 p0 = tp[0], p1 = tp[1], p2 = tp[2], p3 = tp[3];
            a[0] = fma2(p0.x, ww, a[0]); a[1] = fma2(p0.y, ww, a[1]);
            a[2] = fma2(p1.x, ww, a[2]); a[3] = fma2(p1.y, ww, a[3]);
            a[4] = fma2(p2.x, ww, a[4]); a[5] = fma2(p2.y, ww, a[5]);
            a[6] = fma2(p3.x, ww, a[6]); a[7] = fma2(p3.y, ww, a[7]);
        }
        #pragma unroll
        for (int j = 0; j < 8; j++) {
            float lo, hi;
            unpack2(a[j], lo, hi);
            g_x[(n0 + 2 * j) * H3 + c] = lo;
            g_x[(n0 + 2 * j + 1) * H3 + c] = hi;
        }
    }
}

// ---------------------------------------------------------------------------
// Kernel 3: fused edge kernel over TARGET-SORTED edges.
// 32 edges/block via g_perm; warps accumulate messages across runs of equal
// target and flush once per run -> ~8x fewer REDG instructions.
// ---------------------------------------------------------------------------
// dynamic smem layout:
//   h1s   [EPB][HID]            @ 0      (16384 B)
//   wbuf  [2][KCH][H3]          @ 16384  (49152 B)
//   Wf1s  [NRBF*HID]            @ 65536  (10240 B)
//   rbfs  [EPB*NRBF]            @ 75776  (2560 B)
//   bf1s  [HID]                 @ 78336  (512 B)
//   bf2s  [H3]                  @ 78848  (1536 B)
//   cuts  [EPB]                 @ 80384  (128 B)
//   uvs   [EPB*3]               @ 80512  (384 B)
//   srcs  [EPB] int             @ 80896  (128 B)
//   tgts  [EPB] int             @ 81024  (128 B)
//   es    [EPB] int             @ 81152  (128 B)
#define SMEM_EDGE 81280

__global__ __launch_bounds__(256, 2) void edge_kernel(
        const int* __restrict__ ei32, const long long* __restrict__ ei64,
        const float* __restrict__ rbf, const float* __restrict__ uv,
        const float* __restrict__ cut,
        const float* __restrict__ Wf1, const float* __restrict__ bf1,
        const float* __restrict__ Wf2, const float* __restrict__ bf2,
        const float* __restrict__ mu, float* __restrict__ out) {
    extern __shared__ char smem[];
    float* h1s  = (float*)smem;
    float* wbuf = (float*)(smem + 16384);
    float* Wf1s = (float*)(smem + 65536);
    float* rbfs = (float*)(smem + 75776);
    float* bf1s = (float*)(smem + 78336);
    float* bf2s = (float*)(smem + 78848);
    float* cuts = (float*)(smem + 80384);
    float* uvs  = (float*)(smem + 80512);
    int*   srcs = (int*)(smem + 80896);
    int*   tgts = (int*)(smem + 81024);
    int*   es   = (int*)(smem + 81152);

    const int tid = threadIdx.x;
    const int e0 = blockIdx.x * EPB;
    const int F4 = KCH * H3 / 4;  // 1536

    // stage Wf2 chunks 0,1
    const float4* wsrc = (const float4*)Wf2;
    {
        float4* d0 = (float4*)wbuf;
        for (int i = tid; i < F4; i += 256) cp_async16(d0 + i, wsrc + i);
        cp_commit();
        float4* d1 = (float4*)(wbuf + KCH * H3);
        for (int i = tid; i < F4; i += 256) cp_async16(d1 + i, wsrc + F4 + i);
        cp_commit();
    }

    if (tid < EPB) es[tid] = g_perm[e0 + tid];
    for (int i = tid; i < NRBF * HID; i += 256) Wf1s[i] = Wf1[i];
    for (int i = tid; i < H3; i += 256)         bf2s[i] = bf2[i];
    if (tid < HID) bf1s[tid] = bf1[tid];
    __syncthreads();  // es visible

    // per-edge gathers through permutation
    {
        // rbf rows are 80 B = 5 float4 each
        float4* r4 = (float4*)rbfs;
        const float4* rsrc = (const float4*)rbf;
        for (int i = tid; i < EPB * 5; i += 256) {
            int e = es[i / 5];
            r4[i] = __ldg(rsrc + e * 5 + (i % 5));
        }
        for (int i = tid; i < EPB * 3; i += 256) {
            int e = es[i / 3];
            uvs[i] = uv[e * 3 + (i % 3)];
        }
        if (tid < EPB) {
            int e = es[tid];
            cuts[tid] = cut[e];
            if (g_idx64) { tgts[tid] = (int)ei64[e]; srcs[tid] = (int)ei64[N_EDGES + e]; }
            else         { tgts[tid] = ei32[e];      srcs[tid] = ei32[N_EDGES + e]; }
        }
    }
    __syncthreads();

    // Phase A: h1 = silu(rbf@Wf1+bf1)
    for (int i = tid; i < EPB * HID; i += 256) {
        int e = i >> 7, j = i & 127;
        float a = bf1s[j];
        #pragma unroll
        for (int k = 0; k < NRBF; k++) a += rbfs[e * NRBF + k] * Wf1s[k * HID + j];
        h1s[i] = silu_f(a);
    }

    // Phase B: filter GEMM, double-buffered 16-row chunks
    const int warp = tid >> 5, lane = tid & 31;
    const int g = warp >> 2;        // column half (0/1)
    const int eb = (warp & 3) * 8;  // 8 edges per warp
    ull acc[8][3];
    #pragma unroll
    for (int a = 0; a < 8; a++)
        #pragma unroll
        for (int b = 0; b < 3; b++) acc[a][b] = 0ull;

    const int wcol = g * 32 + lane;

    #pragma unroll
    for (int c = 0; c < NCHUNK; c++) {
        if (c == NCHUNK - 1) cp_wait<0>(); else cp_wait<1>();
        __syncthreads();
        const float* wch = wbuf + (c & 1) * KCH * H3;
        const float* hp0 = h1s + eb * HID + c * KCH;
        #pragma unroll
        for (int kk4 = 0; kk4 < KCH; kk4 += 4) {
            float hv[8][4];
            #pragma unroll
            for (int e = 0; e < 8; e++) {
                float4 t = *(const float4*)(hp0 + e * HID + kk4);
                hv[e][0] = t.x; hv[e][1] = t.y; hv[e][2] = t.z; hv[e][3] = t.w;
            }
            #pragma unroll
            for (int j = 0; j < 4; j++) {
                const ull* row = (const ull*)(wch + (kk4 + j) * H3);
                ull wq = row[wcol];
                ull wr = row[64 + wcol];
                ull wm = row[128 + wcol];
                #pragma unroll
                for (int e = 0; e < 8; e++) {
                    ull h2 = pack2(hv[e][j], hv[e][j]);
                    acc[e][0] = fma2(h2, wq, acc[e][0]);
                    acc[e][1] = fma2(h2, wr, acc[e][1]);
                    acc[e][2] = fma2(h2, wm, acc[e][2]);
                }
            }
        }
        __syncthreads();
        if (c + 2 < NCHUNK) {
            float4* d = (float4*)(wbuf + (c & 1) * KCH * H3);
            const float4* s = wsrc + (c + 2) * F4;
            for (int i = tid; i < F4; i += 256) cp_async16(d + i, s + i);
            cp_commit();
        }
    }

    // Phase C: epilogue with run-combined scatter (targets sorted).
    float* outq  = out;
    float* outmu = out + N_NODES * HID;
    const int c0 = g * 64 + lane * 2;

    const float bq0 = bf2s[c0],           bq1 = bf2s[c0 + 1];
    const float br0 = bf2s[HID + c0],     br1 = bf2s[HID + c0 + 1];
    const float bm0 = bf2s[2 * HID + c0], bm1 = bf2s[2 * HID + c0 + 1];

    float sq0 = 0.f, sq1 = 0.f;
    float sv[3][2] = {{0.f,0.f},{0.f,0.f},{0.f,0.f}};

    #pragma unroll
    for (int e8 = 0; e8 < 8; e8++) {
        const int e = eb + e8;
        const float cscale = cuts[e];
        const int src = srcs[e];

        float fq0, fq1, fr0, fr1, fm0, fm1;
        unpack2(acc[e8][0], fq0, fq1);
        unpack2(acc[e8][1], fr0, fr1);
        unpack2(acc[e8][2], fm0, fm1);
        fq0 = (fq0 + bq0) * cscale; fq1 = (fq1 + bq1) * cscale;
        fr0 = (fr0 + br0) * cscale; fr1 = (fr1 + br1) * cscale;
        fm0 = (fm0 + bm0) * cscale; fm1 = (fm1 + bm1) * cscale;

        const float* xb = g_x + src * H3;
        float2 xq = __ldg((const float2*)(xb + c0));
        sq0 += xq.x * fq0; sq1 += xq.y * fq1;

        float2 xr = __ldg((const float2*)(xb + HID + c0));
        float2 xm = __ldg((const float2*)(xb + 2 * HID + c0));
        float xr0 = xr.x * fr0, xr1 = xr.y * fr1;
        float xm0 = xm.x * fm0, xm1 = xm.y * fm1;
        #pragma unroll
        for (int d = 0; d < 3; d++) {
            float u = uvs[e * 3 + d];
            float2 m2 = __ldg((const float2*)(mu + (src * 3 + d) * HID + c0));
            sv[d][0] += u * xr0 + m2.x * xm0;
            sv[d][1] += u * xr1 + m2.y * xm1;
        }

        const int t = tgts[e];
        const bool flush = (e8 == 7) || (tgts[e + 1] != t);  // warp-uniform
        if (flush) {
            red_add_v2(outq + t * HID + c0, sq0, sq1);
            #pragma unroll
            for (int d = 0; d < 3; d++)
                red_add_v2(outmu + (t * 3 + d) * HID + c0, sv[d][0], sv[d][1]);
            sq0 = sq1 = 0.f;
            #pragma unroll
            for (int d = 0; d < 3; d++) { sv[d][0] = 0.f; sv[d][1] = 0.f; }
        }
    }
}

extern "C" void kernel_launch(void* const* d_in, const int* in_sizes, int n_in,
                              void* d_out, int out_size) {
    const float* q   = (const float*)d_in[0];
    const float* mu  = (const float*)d_in[1];
    const void*  ei  = d_in[2];
    const float* rbf = (const float*)d_in[3];
    const float* uvp = (const float*)d_in[4];
    const float* cut = (const float*)d_in[5];
    const float* W1  = (const float*)d_in[6];
    const float* b1  = (const float*)d_in[7];
    const float* W2  = (const float*)d_in[8];
    const float* b2  = (const float*)d_in[9];
    const float* Wf1 = (const float*)d_in[10];
    const float* bf1 = (const float*)d_in[11];
    const float* Wf2 = (const float*)d_in[12];
    const float* bf2 = (const float*)d_in[13];
    float* out = (float*)d_out;

    cudaFuncSetAttribute(edge_kernel,
                         cudaFuncAttributeMaxDynamicSharedMemorySize, SMEM_EDGE);

    const int total4 = N_NODES * (HID + H3) / 4;
    init_out<<<(total4 + 255) / 256, 256>>>(q, mu, out, (const int*)ei);
    hist_kernel<<<(N_EDGES + 255) / 256, 256>>>((const int*)ei, (const long long*)ei);
    scan_kernel<<<1, 1024>>>();
    scatter_kernel<<<(N_EDGES + 255) / 256, 256>>>((const int*)ei, (const long long*)ei);
    node_mlp<<<N_NODES / 16, 384>>>(q, W1, b1, W2, b2);
    edge_kernel<<<N_EDGES / EPB, 256, SMEM_EDGE>>>(
        (const int*)ei, (const long long*)ei,
        rbf, uvp, cut, Wf1, bf1, Wf2, bf2, mu, out);
}

// round 9
// speedup vs baseline: 1.0885x; 1.0885x over previous
#include <cuda_runtime.h>
#include <stdint.h>

#define N_NODES 10000
#define N_EDGES 320000
#define HID 128
#define H3 384
#define NRBF 20
#define EPB 64      // edges per block (edge kernel)
#define KCH 16      // Wf2 k-rows per staged chunk
#define NCHUNK (HID / KCH)   // 8
#define EK_THREADS 512

typedef unsigned long long ull;

// scratch
__device__ float g_x[N_NODES * H3];     // node MLP output [N, 384]
__device__ float g_wf2t[HID * H3];      // Wf2 pre-converted to tf32 bit patterns
__device__ int g_idx64;
__device__ int g_hist[N_NODES];
__device__ int g_cursor[N_NODES];
__device__ int g_perm[N_EDGES];         // edge ids sorted by target

__device__ __forceinline__ float silu_f(float v) {
    return v / (1.0f + __expf(-v));
}
__device__ __forceinline__ ull pack2(float lo, float hi) {
    ull r;
    asm("mov.b64 %0,{%1,%2};" : "=l"(r) : "f"(lo), "f"(hi));
    return r;
}
__device__ __forceinline__ void unpack2(ull v, float& lo, float& hi) {
    asm("mov.b64 {%0,%1},%2;" : "=f"(lo), "=f"(hi) : "l"(v));
}
__device__ __forceinline__ ull fma2(ull a, ull b, ull c) {
    ull d;
    asm("fma.rn.f32x2 %0,%1,%2,%3;" : "=l"(d) : "l"(a), "l"(b), "l"(c));
    return d;
}
__device__ __forceinline__ uint32_t f2tf32(float f) {
    uint32_t r;
    asm("cvt.rna.tf32.f32 %0,%1;" : "=r"(r) : "f"(f));
    return r;
}
__device__ __forceinline__ void mma_tf32(float* d, const uint32_t* a, const uint32_t* b) {
    asm("mma.sync.aligned.m16n8k8.row.col.f32.tf32.tf32.f32 "
        "{%0,%1,%2,%3},{%4,%5,%6,%7},{%8,%9},{%0,%1,%2,%3};"
        : "+f"(d[0]), "+f"(d[1]), "+f"(d[2]), "+f"(d[3])
        : "r"(a[0]), "r"(a[1]), "r"(a[2]), "r"(a[3]), "r"(b[0]), "r"(b[1]));
}
__device__ __forceinline__ void red_add_v2(float* p, float a, float b) {
    asm volatile("red.global.add.v2.f32 [%0],{%1,%2};"
                 :: "l"(p), "f"(a), "f"(b) : "memory");
}
__device__ __forceinline__ void cp_async16(void* sdst, const void* gsrc) {
    unsigned s = (unsigned)__cvta_generic_to_shared(sdst);
    asm volatile("cp.async.cg.shared.global [%0],[%1],16;" :: "r"(s), "l"(gsrc));
}
__device__ __forceinline__ void cp_commit() {
    asm volatile("cp.async.commit_group;");
}
template <int N>
__device__ __forceinline__ void cp_wait() {
    asm volatile("cp.async.wait_group %0;" :: "n"(N));
}

// sorted position s for physical MMA row R (bijection on [0,64))
__device__ __forceinline__ int sorted_of_row(int R) {
    return 8 * (R & 7) + ((R >> 4) << 1) + ((R >> 3) & 1);
}

// ---------------------------------------------------------------------------
// Kernel 1: out = concat(q, mu); detect idx dtype; zero histogram.
// ---------------------------------------------------------------------------
__global__ void init_out(const float* __restrict__ q,
                         const float* __restrict__ mu,
                         float* __restrict__ out,
                         const int* __restrict__ ei32) {
    if (blockIdx.x == 0 && threadIdx.x == 0) {
        int flag = 1;
        #pragma unroll
        for (int i = 0; i < 16; i++)
            if (ei32[2 * i + 1] != 0) flag = 0;
        g_idx64 = flag;
    }
    int i = blockIdx.x * blockDim.x + threadIdx.x;
    if (i < N_NODES) g_hist[i] = 0;
    const int nq4 = N_NODES * HID / 4;
    const int nm4 = N_NODES * H3 / 4;
    float4* o4 = (float4*)out;
    if (i < nq4)            o4[i] = ((const float4*)q)[i];
    else if (i < nq4 + nm4) o4[i] = ((const float4*)mu)[i - nq4];
}

__global__ void prep_wf2(const float* __restrict__ Wf2) {
    int i = blockIdx.x * blockDim.x + threadIdx.x;
    if (i < HID * H3) g_wf2t[i] = __uint_as_float(f2tf32(Wf2[i]));
}

// --------------------------- counting sort by target -----------------------
__global__ void hist_kernel(const int* __restrict__ ei32,
                            const long long* __restrict__ ei64) {
    int e = blockIdx.x * blockDim.x + threadIdx.x;
    if (e < N_EDGES) {
        int t = g_idx64 ? (int)ei64[e] : ei32[e];
        atomicAdd(&g_hist[t], 1);
    }
}

__global__ __launch_bounds__(1024) void scan_kernel() {
    __shared__ int part[1024];
    const int tid = threadIdx.x;
    const int base = tid * 10;
    int local[10];
    int s = 0;
    #pragma unroll
    for (int j = 0; j < 10; j++) {
        int v = (base + j < N_NODES) ? g_hist[base + j] : 0;
        local[j] = s;
        s += v;
    }
    part[tid] = s;
    __syncthreads();
    const int own = s;
    for (int d = 1; d < 1024; d <<= 1) {
        int v = (tid >= d) ? part[tid - d] : 0;
        __syncthreads();
        part[tid] += v;
        __syncthreads();
    }
    int excl = part[tid] - own;
    #pragma unroll
    for (int j = 0; j < 10; j++)
        if (base + j < N_NODES) g_cursor[base + j] = excl + local[j];
}

__global__ void scatter_kernel(const int* __restrict__ ei32,
                               const long long* __restrict__ ei64) {
    int e = blockIdx.x * blockDim.x + threadIdx.x;
    if (e < N_EDGES) {
        int t = g_idx64 ? (int)ei64[e] : ei32[e];
        int pos = atomicAdd(&g_cursor[t], 1);
        g_perm[pos] = e;
    }
}

// ---------------------------------------------------------------------------
// Kernel 2: node MLP (unchanged). 16 nodes/block.
// ---------------------------------------------------------------------------
__global__ __launch_bounds__(384) void node_mlp(const float* __restrict__ q,
                                                const float* __restrict__ W1,
                                                const float* __restrict__ b1,
                                                const float* __restrict__ W2,
                                                const float* __restrict__ b2) {
    __shared__ float qs[16 * HID];
    __shared__ ull qs2[HID * 8];
    __shared__ ull t1p[H3 * 8];
    const int n0 = blockIdx.x * 16;
    const int tid = threadIdx.x;

    for (int i = tid; i < 16 * HID; i += 384) qs[i] = q[n0 * HID + i];
    __syncthreads();
    for (int i = tid; i < HID * 8; i += 384) {
        int k = i >> 3, j = i & 7;
        qs2[k * 8 + j] = pack2(qs[(2 * j) * HID + k], qs[(2 * j + 1) * HID + k]);
    }
    __syncthreads();

    const int c = tid;
    {
        ull a[8];
        float bb = __ldg(&b1[c]);
        ull bp = pack2(bb, bb);
        #pragma unroll
        for (int j = 0; j < 8; j++) a[j] = bp;
        #pragma unroll 4
        for (int k = 0; k < HID; k++) {
            float w = __ldg(&W1[k * H3 + c]);
            ull ww = pack2(w, w);
            const ulonglong2* qp = (const ulonglong2*)(qs2 + k * 8);
            ulonglong2 p0 = qp[0], p1 = qp[1], p2 = qp[2], p3 = qp[3];
            a[0] = fma2(p0.x, ww, a[0]); a[1] = fma2(p0.y, ww, a[1]);
            a[2] = fma2(p1.x, ww, a[2]); a[3] = fma2(p1.y, ww, a[3]);
            a[4] = fma2(p2.x, ww, a[4]); a[5] = fma2(p2.y, ww, a[5]);
            a[6] = fma2(p3.x, ww, a[6]); a[7] = fma2(p3.y, ww, a[7]);
        }
        #pragma unroll
        for (int j = 0; j < 8; j++) {
            float lo, hi;
            unpack2(a[j], lo, hi);
            t1p[c * 8 + j] = pack2(silu_f(lo), silu_f(hi));
        }
    }
    __syncthreads();
    {
        ull a[8];
        float bb = __ldg(&b2[c]);
        ull bp = pack2(bb, bb);
        #pragma unroll
        for (int j = 0; j < 8; j++) a[j] = bp;
        #pragma unroll 4
        for (int k = 0; k < H3; k++) {
            float w = __ldg(&W2[k * H3 + c]);
            ull ww = pack2(w, w);
            const ulonglong2* tp = (const ulonglong2*)(t1p + k * 8);
            ulonglong2 p0 = tp[0], p1 = tp[1], p2 = tp[2], p3 = tp[3];
            a[0] = fma2(p0.x, ww, a[0]); a[1] = fma2(p0.y, ww, a[1]);
            a[2] = fma2(p1.x, ww, a[2]); a[3] = fma2(p1.y, ww, a[3]);
            a[4] = fma2(p2.x, ww, a[4]); a[5] = fma2(p2.y, ww, a[5]);
            a[6] = fma2(p3.x, ww, a[6]); a[7] = fma2(p3.y, ww, a[7]);
        }
        #pragma unroll
        for (int j = 0; j < 8; j++) {
            float lo, hi;
            unpack2(a[j], lo, hi);
            g_x[(n0 + 2 * j) * H3 + c] = lo;
            g_x[(n0 + 2 * j + 1) * H3 + c] = hi;
        }
    }
}

// ---------------------------------------------------------------------------
// Kernel 3: fused edge kernel — TF32 tensor-core filter GEMM.
// 64 target-sorted edges/block, 512 threads, 16 warps.
// Each warp: 3 n8-tiles (24 cols) x 4 m16-tiles (all 64 edges), K=128.
// Wf2 (tf32-preconverted) staged via cp.async into XOR-swizzled chunks.
// MMA rows permuted so each lane's 8 epilogue edges are sorted-consecutive
// (run-combined red.v2 scatter).
// ---------------------------------------------------------------------------
// dynamic smem layout:
//   h1s   [64][132] float (tf32 bits) @ 0       (33792 B)
//   wbuf  [2][16][384] float          @ 33792   (49152 B)
//   Wf1s  [NRBF*HID]                  @ 82944   (10240 B)
//   rbfs  [64*NRBF]  (physical rows)  @ 93184   (5120 B)
//   bf1s  [HID]                       @ 98304   (512 B)
//   bf2s  [H3]                        @ 98816   (1536 B)
//   cuts  [64]  (sorted order)        @ 100352  (256 B)
//   uvs   [64*3] (sorted)             @ 100608  (768 B)
//   srcs  [64] int (sorted)           @ 101376  (256 B)
//   tgts  [64] int (sorted)           @ 101632  (256 B)
//   es    [64] int (sorted edge ids)  @ 101888  (256 B)
#define SMEM_EDGE 102144
#define H1PITCH 132

__global__ __launch_bounds__(EK_THREADS) void edge_kernel(
        const int* __restrict__ ei32, const long long* __restrict__ ei64,
        const float* __restrict__ rbf, const float* __restrict__ uv,
        const float* __restrict__ cut,
        const float* __restrict__ Wf1, const float* __restrict__ bf1,
        const float* __restrict__ bf2,
        const float* __restrict__ mu, float* __restrict__ out) {
    extern __shared__ char smem[];
    float*    h1s  = (float*)smem;
    uint32_t* h1u  = (uint32_t*)smem;
    float*    wbuf = (float*)(smem + 33792);
    float*    Wf1s = (float*)(smem + 82944);
    float*    rbfs = (float*)(smem + 93184);
    float*    bf1s = (float*)(smem + 98304);
    float*    bf2s = (float*)(smem + 98816);
    float*    cuts = (float*)(smem + 100352);
    float*    uvs  = (float*)(smem + 100608);
    int*      srcs = (int*)(smem + 101376);
    int*      tgts = (int*)(smem + 101632);
    int*      es   = (int*)(smem + 101888);

    const int tid = threadIdx.x;
    const int e0 = blockIdx.x * EPB;
    const int F4 = KCH * H3 / 4;  // 1536 float4 per chunk

    // swizzled cp.async staging of a Wf2 chunk (tf32-preconverted source)
    auto stage_chunk = [&](int chunk, int buf) {
        float* dst = wbuf + buf * KCH * H3;
        const float4* src = (const float4*)g_wf2t + chunk * F4;
        for (int i = tid; i < F4; i += EK_THREADS) {
            int kk = i / 96;          // 96 float4 per 384-float row
            int n  = (i % 96) * 4;
            int ns = n ^ ((kk & 3) << 3);
            cp_async16(dst + kk * H3 + ns, src + i);
        }
        cp_commit();
    };

    stage_chunk(0, 0);
    stage_chunk(1, 1);

    if (tid < EPB) es[tid] = g_perm[e0 + tid];
    for (int i = tid; i < NRBF * HID; i += EK_THREADS) Wf1s[i] = Wf1[i];
    for (int i = tid; i < H3; i += EK_THREADS)         bf2s[i] = bf2[i];
    if (tid < HID) bf1s[tid] = bf1[tid];
    __syncthreads();  // es visible

    // per-edge gathers; rbf by PHYSICAL mma row, rest by sorted order
    {
        float4* r4 = (float4*)rbfs;
        const float4* rsrc = (const float4*)rbf;
        for (int i = tid; i < EPB * 5; i += EK_THREADS) {
            int R = i / 5;
            int e = es[sorted_of_row(R)];
            r4[i] = __ldg(rsrc + e * 5 + (i % 5));
        }
        for (int i = tid; i < EPB * 3; i += EK_THREADS) {
            int e = es[i / 3];
            uvs[i] = uv[e * 3 + (i % 3)];
        }
        if (tid < EPB) {
            int e = es[tid];
            cuts[tid] = cut[e];
            if (g_idx64) { tgts[tid] = (int)ei64[e]; srcs[tid] = (int)ei64[N_EDGES + e]; }
            else         { tgts[tid] = ei32[e];      srcs[tid] = ei32[N_EDGES + e]; }
        }
    }
    __syncthreads();

    // Phase A: h1 = tf32(silu(rbf@Wf1+bf1)), physical rows, pitch 132
    for (int i = tid; i < EPB * HID; i += EK_THREADS) {
        int R = i >> 7, j = i & 127;
        float a = bf1s[j];
        #pragma unroll
        for (int k = 0; k < NRBF; k++) a += rbfs[R * NRBF + k] * Wf1s[k * HID + j];
        h1u[R * H1PITCH + j] = f2tf32(silu_f(a));
    }

    // Phase B: TF32 MMA. warp w owns cols [w*24, w*24+24) = 3 n8-tiles.
    const int warp = tid >> 5, lane = tid & 31;
    const int g = lane >> 2, c = lane & 3;
    const int C0 = warp * 24;

    float d[4][3][4];
    #pragma unroll
    for (int mt = 0; mt < 4; mt++)
        #pragma unroll
        for (int j = 0; j < 3; j++)
            #pragma unroll
            for (int r = 0; r < 4; r++) d[mt][j][r] = 0.f;

    #pragma unroll
    for (int chunk = 0; chunk < NCHUNK; chunk++) {
        if (chunk == NCHUNK - 1) cp_wait<0>(); else cp_wait<1>();
        __syncthreads();   // chunk ready (and h1 ready for chunk 0)
        const float* wch = wbuf + (chunk & 1) * KCH * H3;
        #pragma unroll
        for (int ks = 0; ks < 2; ks++) {
            const int kglob = chunk * KCH + 8 * ks;
            uint32_t a[4][4];
            #pragma unroll
            for (int mt = 0; mt < 4; mt++) {
                const uint32_t* hp = h1u + (16 * mt + g) * H1PITCH + kglob + c;
                a[mt][0] = hp[0];
                a[mt][1] = hp[8 * H1PITCH];
                a[mt][2] = hp[4];
                a[mt][3] = hp[8 * H1PITCH + 4];
            }
            uint32_t b[3][2];
            #pragma unroll
            for (int j = 0; j < 3; j++) {
                const int n = C0 + 8 * j + g;
                const int kk0 = 8 * ks + c;
                b[j][0] = ((const uint32_t*)wch)[kk0 * H3 + (n ^ ((kk0 & 3) << 3))];
                const int kk1 = kk0 + 4;
                b[j][1] = ((const uint32_t*)wch)[kk1 * H3 + (n ^ ((kk1 & 3) << 3))];
            }
            #pragma unroll
            for (int mt = 0; mt < 4; mt++)
                #pragma unroll
                for (int j = 0; j < 3; j++)
                    mma_tf32(d[mt][j], a[mt], b[j]);
        }
        __syncthreads();   // all warps done with buffer (chunk&1)
        if (chunk + 2 < NCHUNK) stage_chunk(chunk + 2, chunk & 1);
    }

    // Phase C: epilogue. Lane owns sorted edges s = 8g+idx, idx 0..7;
    // physical row R = 16*(idx>>1) + 8*(idx&1) + g. Run-combined scatter.
    float* outq  = out;
    float* outmu = out + N_NODES * HID;

    int   part[3], jj[3];
    float bb0[3], bb1[3];
    #pragma unroll
    for (int j = 0; j < 3; j++) {
        int C = C0 + 8 * j + 2 * c;
        part[j] = C >> 7;
        jj[j]   = C & 127;
        bb0[j] = bf2s[C];
        bb1[j] = bf2s[C + 1];
    }

    float acc[3][3][2];
    #pragma unroll
    for (int j = 0; j < 3; j++)
        #pragma unroll
        for (int dd = 0; dd < 3; dd++) { acc[j][dd][0] = 0.f; acc[j][dd][1] = 0.f; }

    #pragma unroll
    for (int idx = 0; idx < 8; idx++) {
        const int s = 8 * g + idx;
        const int mt = idx >> 1, h = idx & 1;
        const float cscale = cuts[s];
        const int src = srcs[s], tgt = tgts[s];
        const float* xb = g_x + src * H3;

        #pragma unroll
        for (int j = 0; j < 3; j++) {
            float f0 = (d[mt][j][2 * h]     + bb0[j]) * cscale;
            float f1 = (d[mt][j][2 * h + 1] + bb1[j]) * cscale;
            if (part[j] == 0) {
                float2 x2 = __ldg((const float2*)(xb + jj[j]));
                acc[j][0][0] += x2.x * f0;
                acc[j][0][1] += x2.y * f1;
            } else if (part[j] == 1) {
                float2 x2 = __ldg((const float2*)(xb + HID + jj[j]));
                float t0 = x2.x * f0, t1 = x2.y * f1;
                #pragma unroll
                for (int dd = 0; dd < 3; dd++) {
                    float u = uvs[s * 3 + dd];
                    acc[j][dd][0] += u * t0;
                    acc[j][dd][1] += u * t1;
                }
            } else {
                float2 x2 = __ldg((const float2*)(xb + 2 * HID + jj[j]));
                float t0 = x2.x * f0, t1 = x2.y * f1;
                #pragma unroll
                for (int dd = 0; dd < 3; dd++) {
                    float2 m2 = __ldg((const float2*)(mu + (src * 3 + dd) * HID + jj[j]));
                    acc[j][dd][0] += m2.x * t0;
                    acc[j][dd][1] += m2.y * t1;
                }
            }
        }

        const bool flush = (idx == 7) || (tgts[s + 1] != tgt);
        if (flush) {
            #pragma unroll
            for (int j = 0; j < 3; j++) {
                if (part[j] == 0) {
                    red_add_v2(outq + tgt * HID + jj[j], acc[j][0][0], acc[j][0][1]);
                    acc[j][0][0] = 0.f; acc[j][0][1] = 0.f;
                } else {
                    #pragma unroll
                    for (int dd = 0; dd < 3; dd++) {
                        red_add_v2(outmu + (tgt * 3 + dd) * HID + jj[j],
                                   acc[j][dd][0], acc[j][dd][1]);
                        acc[j][dd][0] = 0.f; acc[j][dd][1] = 0.f;
                    }
                }
            }
        }
    }
}

extern "C" void kernel_launch(void* const* d_in, const int* in_sizes, int n_in,
                              void* d_out, int out_size) {
    const float* q   = (const float*)d_in[0];
    const float* mu  = (const float*)d_in[1];
    const void*  ei  = d_in[2];
    const float* rbf = (const float*)d_in[3];
    const float* uvp = (const float*)d_in[4];
    const float* cut = (const float*)d_in[5];
    const float* W1  = (const float*)d_in[6];
    const float* b1  = (const float*)d_in[7];
    const float* W2  = (const float*)d_in[8];
    const float* b2  = (const float*)d_in[9];
    const float* Wf1 = (const float*)d_in[10];
    const float* bf1 = (const float*)d_in[11];
    const float* Wf2 = (const float*)d_in[12];
    const float* bf2 = (const float*)d_in[13];
    float* out = (float*)d_out;

    cudaFuncSetAttribute(edge_kernel,
                         cudaFuncAttributeMaxDynamicSharedMemorySize, SMEM_EDGE);

    const int total4 = N_NODES * (HID + H3) / 4;
    init_out<<<(total4 + 255) / 256, 256>>>(q, mu, out, (const int*)ei);
    prep_wf2<<<(HID * H3 + 255) / 256, 256>>>(Wf2);
    hist_kernel<<<(N_EDGES + 255) / 256, 256>>>((const int*)ei, (const long long*)ei);
    scan_kernel<<<1, 1024>>>();
    scatter_kernel<<<(N_EDGES + 255) / 256, 256>>>((const int*)ei, (const long long*)ei);
    node_mlp<<<N_NODES / 16, 384>>>(q, W1, b1, W2, b2);
    edge_kernel<<<N_EDGES / EPB, EK_THREADS, SMEM_EDGE>>>(
        (const int*)ei, (const long long*)ei,
        rbf, uvp, cut, Wf1, bf1, bf2, mu, out);
}